// round 10
// baseline (speedup 1.0000x reference)
#include <cuda_runtime.h>
#include <math.h>

// DTW 2048x2048, out = sqrt(DTW[N-1][N-1]).
// v[i][j] = (x[i]-y[j])^2 + min(up,left,diag); border v[-1][-1]=0 else inf.
//
// R8 = R1 shape + R7 tile schedule:
//  - NT=256 threads (8 warps -> 2 per SMSP: co-resident warp hides LDS/chain/
//    barrier-jitter bubbles; R1 measured only ~96 cyc/step overhead in this
//    shape vs ~143 at 1 warp/SMSP).
//  - stage t owns NC=8 cols; rows in NR=4 chunks; NS = 255+512 = 767 steps,
//    one __syncthreads per step, edge via double-buffered smem strip.
//  - stagger-1 intra-tile wavefront (R7, rel_err 0.0): chain 11*10=110 cyc
//    << 272-cyc per-SMSP issue floor -> issue-bound.
//  - activity guard kept (R3 lesson: junk tiles burn the scarce issue slots).
// Per-cell arithmetic token-identical to R1/R5/R7 -> bitwise-identical result.

#define NT   256
#define NC   8
#define NR   4
#define LEN  2048
#define NK   (LEN / NR)     // 512
#define NS   (NT - 1 + NK)  // 767

__global__ __launch_bounds__(NT, 1)
void dtw_kernel(const float* __restrict__ x,
                const float* __restrict__ y,
                float* __restrict__ out)
{
    __shared__ float  xs[LEN];          // 8 KB
    __shared__ float4 buf[2][NT + 1];   // edge double-buffer, slot 0 == +inf

    const int   t   = threadIdx.x;
    const float INF = __int_as_float(0x7f800000);

    // Preload x (visible after first barrier).
    {
        const float4* x4  = reinterpret_cast<const float4*>(x);
        float4*       xs4 = reinterpret_cast<float4*>(xs);
        #pragma unroll
        for (int i = t; i < LEN / 4; i += NT) xs4[i] = x4[i];
    }
    // Edge buffers start at INF; slot 0 is never overwritten and provides the
    // global left boundary (column -1 = +inf). INF slots also serve the fill
    // phase reads of not-yet-active neighbors (guard makes them unused anyway).
    buf[0][t] = make_float4(INF, INF, INF, INF);
    buf[1][t] = make_float4(INF, INF, INF, INF);
    if (t == 0) {
        buf[0][NT] = make_float4(INF, INF, INF, INF);
        buf[1][NT] = make_float4(INF, INF, INF, INF);
    }

    // This thread's 8 y columns.
    float yc[NC];
    {
        const float4* y4 = reinterpret_cast<const float4*>(y + t * NC);
        float4 a = y4[0], b = y4[1];
        yc[0] = a.x; yc[1] = a.y; yc[2] = a.z; yc[3] = a.w;
        yc[4] = b.x; yc[5] = b.y; yc[6] = b.z; yc[7] = b.w;
    }

    float prev[NC];
    #pragma unroll
    for (int c = 0; c < NC; c++) prev[c] = INF;

    float  diag_edge = (t == 0) ? 0.0f : INF;
    float4 vout      = make_float4(INF, INF, INF, INF);

    for (int s = 0; s < NS; s++) {
        __syncthreads();
        const int k = s - t;
        if (k >= 0 && k < NK) {
            // Left edge: thread t-1's previous-step output (slot t; slot 0=INF).
            const float4 ev = buf[(s - 1) & 1][t];
            const float4 xv = *reinterpret_cast<const float4*>(xs + (k << 2));

            const float xr[NR] = {xv.x, xv.y, xv.z, xv.w};
            const float e[NR]  = {ev.x, ev.y, ev.z, ev.w};

            float left[NR], dgr[NR];
            left[0] = e[0]; left[1] = e[1]; left[2] = e[2]; left[3] = e[3];
            dgr[0]  = diag_edge; dgr[1] = e[0]; dgr[2] = e[1]; dgr[3] = e[2];
            diag_edge = e[NR - 1];

            // Stagger-1 intra-tile wavefront: slot jj does cells (i, jj-i);
            // left/up deps land 1 slot earlier, diag 2 -> 4 concurrent chains.
            #pragma unroll
            for (int jj = 0; jj < NC + NR - 1; jj++) {
                #pragma unroll
                for (int i = 0; i < NR; i++) {
                    const int j = jj - i;        // compile-time after unroll
                    if (j >= 0 && j < NC) {
                        float d  = xr[i] - yc[j];
                        float up = prev[j];
                        float m  = fminf(fminf(up, dgr[i]), left[i]);
                        float v  = fmaf(d, d, m);
                        dgr[i]  = up;
                        prev[j] = v;
                        left[i] = v;
                    }
                }
            }

            vout = make_float4(left[0], left[1], left[2], left[3]);
            buf[s & 1][t + 1] = vout;
        }
    }

    // Thread 255's final step (s = NS-1, chunk NK-1): vout.w = v[2047][2047].
    if (t == NT - 1) out[0] = sqrtf(vout.w);
}

extern "C" void kernel_launch(void* const* d_in, const int* in_sizes, int n_in,
                              void* d_out, int out_size)
{
    const float* x = (const float*)d_in[0];
    const float* y = (const float*)d_in[1];
    float* out = (float*)d_out;
    (void)in_sizes; (void)n_in; (void)out_size;
    dtw_kernel<<<1, NT>>>(x, y, out);
}